// round 3
// baseline (speedup 1.0000x reference)
#include <cuda_runtime.h>

#define B 8
#define M 2048
#define N 2048
#define IN 256
#define TM 32
#define TN 1024
#define TMC 32

// ---- scratch (allocation-free: __device__ globals) ----
__device__ float g_v0[IN];          // W0^T @ Wc[:128]
__device__ float g_v1[IN];          // W1^T @ Wc[128:]
__device__ float g_consts[2];       // dot(b0,wc0) ; dot(b1,wc1)+bc
__device__ float g_s0[B * M];       // s0 + const0
__device__ float g_ls0[B * M];      // logsig(z0)
__device__ float g_lsn0[B * M];     // logsig(-z0)
__device__ float g_s1b[B * N];      // s1 + const1 (bc folded in)
__device__ float g_ls1[B * N];      // logsig(z1)
__device__ float g_lsn1[B * N];     // logsig(-z1)

__device__ __forceinline__ float lsig(float x) {
    // log_sigmoid(x) = min(x,0) - log1p(exp(-|x|)); fast-math variant.
    return fminf(x, 0.0f) - __logf(1.0f + __expf(-fabsf(x)));
}

// ---- kernel 0: fold projection weights through Wc; compute bias constants ----
__global__ void prep_kernel(const float* __restrict__ W0, const float* __restrict__ b0,
                            const float* __restrict__ W1, const float* __restrict__ b1,
                            const float* __restrict__ Wc, const float* __restrict__ bc) {
    int i = threadIdx.x;  // 0..255
    float a0 = 0.f, a1 = 0.f;
    #pragma unroll 8
    for (int d = 0; d < 128; d++) {
        a0 += W0[d * IN + i] * Wc[d];
        a1 += W1[d * IN + i] * Wc[128 + d];
    }
    g_v0[i] = a0;
    g_v1[i] = a1;

    int w = i >> 5, l = i & 31;
    if (w == 0) {
        float c = 0.f;
        for (int d = l; d < 128; d += 32) c += b0[d] * Wc[d];
        #pragma unroll
        for (int o = 16; o; o >>= 1) c += __shfl_down_sync(0xffffffffu, c, o);
        if (l == 0) g_consts[0] = c;
    } else if (w == 1) {
        float c = 0.f;
        for (int d = l; d < 128; d += 32) c += b1[d] * Wc[128 + d];
        #pragma unroll
        for (int o = 16; o; o >>= 1) c += __shfl_down_sync(0xffffffffu, c, o);
        if (l == 0) g_consts[1] = c + bc[0];
    }
}

// ---- kernel 1: per-row dot products; one warp per row ----
__global__ void rows_kernel(const float* __restrict__ d0, const float* __restrict__ d1,
                            const float* __restrict__ Wm, const float* __restrict__ bm) {
    int which = blockIdx.y;                 // 0 -> desc0, 1 -> desc1
    const float* desc = which ? d1 : d0;
    const float* v    = which ? g_v1 : g_v0;
    int warp = threadIdx.x >> 5, lane = threadIdx.x & 31;
    int row = blockIdx.x * 8 + warp;        // B*M rows total

    const float4* dp = (const float4*)(desc + (size_t)row * IN);
    const float4* vp = (const float4*)v;
    const float4* wp = (const float4*)Wm;

    float as = 0.f, az = 0.f;
    #pragma unroll
    for (int j = 0; j < 2; j++) {
        int k = lane + j * 32;              // 64 float4 per row
        float4 dv = dp[k];
        float4 vv = vp[k];
        float4 wv = wp[k];
        as += dv.x * vv.x + dv.y * vv.y + dv.z * vv.z + dv.w * vv.w;
        az += dv.x * wv.x + dv.y * wv.y + dv.z * wv.z + dv.w * wv.w;
    }
    #pragma unroll
    for (int o = 16; o; o >>= 1) {
        as += __shfl_down_sync(0xffffffffu, as, o);
        az += __shfl_down_sync(0xffffffffu, az, o);
    }
    if (lane == 0) {
        float z = az + bm[0];
        if (which == 0) {
            g_s0[row]  = as + g_consts[0];
            g_ls0[row] = lsig(z);
            g_lsn0[row] = lsig(-z);
        } else {
            g_s1b[row] = as + g_consts[1];
            g_ls1[row] = lsig(z);
            g_lsn1[row] = lsig(-z);
        }
    }
}

// ---- kernel 2a: corres, fully vectorized float4 stores ----
// corres rows have stride 2048 and the corres base is 16B aligned, so each
// thread owns 4 consecutive columns and stores one STG.128 per row.
__global__ void __launch_bounds__(256) corres_kernel(float* __restrict__ corres) {
    int b  = blockIdx.z;
    int m0 = blockIdx.y * TMC;
    int n  = blockIdx.x * TN + threadIdx.x * 4;
    int tx = threadIdx.x;

    __shared__ float sh_s0[TMC];
    if (tx < TMC) sh_s0[tx] = g_s0[b * M + m0 + tx];

    float4 s1 = *(const float4*)(g_s1b + b * N + n);
    __syncthreads();

    float4* p = (float4*)(corres + (size_t)b * M * N + (size_t)m0 * N + n);
    #pragma unroll 4
    for (int r = 0; r < TMC; r++) {
        float s0 = sh_s0[r];
        float4 v = make_float4(s0 + s1.x, s0 + s1.y, s0 + s1.z, s0 + s1.w);
        *p = v;
        p += N / 4;
    }
}

// ---- kernel 2b: probs inner region (+ fused right-edge column) ----
// Scalar coalesced stores (probs row stride 2049 breaks 16B alignment).
// Thread t owns columns n0 + t + j*256.
__global__ void __launch_bounds__(256) probs_kernel(float* __restrict__ probs) {
    int b  = blockIdx.z;
    int m0 = blockIdx.y * TM;
    int n0 = blockIdx.x * TN;
    int tx = threadIdx.x;

    __shared__ float sh_s0[TM];
    __shared__ float sh_ls0[TM];
    if (tx < TM) {
        int r = b * M + m0 + tx;
        sh_s0[tx]  = g_s0[r];
        sh_ls0[tx] = g_ls0[r];
    }

    float s1v[4], ls1v[4];
    #pragma unroll
    for (int j = 0; j < 4; j++) {
        int n = n0 + tx + j * 256;
        s1v[j]  = g_s1b[b * N + n];
        ls1v[j] = g_ls1[b * N + n];
    }
    __syncthreads();

    size_t pbase = (size_t)b * (M + 1) * (N + 1);
    float* prow = probs + pbase + (size_t)m0 * (N + 1) + n0 + tx;

    #pragma unroll 4
    for (int r = 0; r < TM; r++) {
        float s0 = sh_s0[r];
        float l0 = sh_ls0[r];
        #pragma unroll
        for (int j = 0; j < 4; j++) {
            float c = s0 + s1v[j];
            prow[j * 256] = lsig(c) + l0 + ls1v[j];
        }
        prow += (N + 1);
    }

    // fused right-edge column: probs[b, m0..m0+TM, N] = logsig(-z0)
    if (blockIdx.x == (N / TN - 1) && tx < TM) {
        probs[pbase + (size_t)(m0 + tx) * (N + 1) + N] = g_lsn0[b * M + m0 + tx];
    }
}

// ---- kernel 3: bottom row of probs (coalesced) ----
__global__ void bottom_kernel(float* __restrict__ probs) {
    int idx = blockIdx.x * blockDim.x + threadIdx.x;  // over B*(N+1)
    if (idx >= B * (N + 1)) return;
    int b = idx / (N + 1), n = idx % (N + 1);
    size_t pbase = (size_t)b * (M + 1) * (N + 1) + (size_t)M * (N + 1);
    probs[pbase + n] = (n < N) ? g_lsn1[b * N + n] : 0.0f;
}

extern "C" void kernel_launch(void* const* d_in, const int* in_sizes, int n_in,
                              void* d_out, int out_size) {
    const float* desc0 = (const float*)d_in[0];
    const float* desc1 = (const float*)d_in[1];
    const float* W0    = (const float*)d_in[2];
    const float* b0    = (const float*)d_in[3];
    const float* W1    = (const float*)d_in[4];
    const float* b1    = (const float*)d_in[5];
    const float* Wm    = (const float*)d_in[6];
    const float* bm    = (const float*)d_in[7];
    const float* Wc    = (const float*)d_in[8];
    const float* bc    = (const float*)d_in[9];

    float* out = (float*)d_out;
    long long probs_elems  = (long long)B * (M + 1) * (N + 1);
    long long corres_elems = (long long)B * M * N;
    int has_corres = ((long long)out_size >= probs_elems + corres_elems) ? 1 : 0;
    float* probs  = out;
    float* corres = out + probs_elems;

    prep_kernel<<<1, 256>>>(W0, b0, W1, b1, Wc, bc);
    rows_kernel<<<dim3(B * M / 8, 2), 256>>>(desc0, desc1, Wm, bm);
    if (has_corres)
        corres_kernel<<<dim3(N / TN, M / TMC, B), 256>>>(corres);
    probs_kernel<<<dim3(N / TN, M / TM, B), 256>>>(probs);
    bottom_kernel<<<(B * (N + 1) + 255) / 256, 256>>>(probs);
}

// round 4
// speedup vs baseline: 1.0217x; 1.0217x over previous
#include <cuda_runtime.h>

#define B 8
#define M 2048
#define N 2048
#define IN 256
#define TM 32
#define TN 1024

// ---- scratch (allocation-free: __device__ globals) ----
__device__ float g_v0[IN];
__device__ float g_v1[IN];
__device__ float g_consts[2];
__device__ float g_s0[B * M];       // s0 + const0
__device__ float g_ls0[B * M];      // logsig(z0)
__device__ float g_lsn0[B * M];     // logsig(-z0)
__device__ float g_s1b[B * N];      // s1 + const1 (bc folded)
__device__ float g_ls1[B * N];      // logsig(z1)
__device__ float g_lsn1[B * N];     // logsig(-z1)

typedef unsigned long long ull;

// ---- f32x2 packed helpers (Blackwell) ----
__device__ __forceinline__ ull pk2(float lo, float hi) {
    ull r; asm("mov.b64 %0, {%1, %2};" : "=l"(r) : "f"(lo), "f"(hi)); return r;
}
__device__ __forceinline__ float2 upk2(ull v) {
    float2 f; asm("mov.b64 {%0, %1}, %2;" : "=f"(f.x), "=f"(f.y) : "l"(v)); return f;
}
__device__ __forceinline__ ull add2_(ull a, ull b) {
    ull d; asm("add.rn.f32x2 %0, %1, %2;" : "=l"(d) : "l"(a), "l"(b)); return d;
}
__device__ __forceinline__ ull fma2_(ull a, ull b, ull c) {
    ull d; asm("fma.rn.f32x2 %0, %1, %2, %3;" : "=l"(d) : "l"(a), "l"(b), "l"(c)); return d;
}
__device__ __forceinline__ float ex2_(float x) {
    float r; asm("ex2.approx.f32 %0, %1;" : "=f"(r) : "f"(x)); return r;
}

// Negated coefficients of deg-6 minimax-ish poly for ln(1+u), u in [0,1]
// (shifted-Chebyshev expansion, rho = 3-2*sqrt(2); abs err < ~5e-6).
#define PC0 (-1.79e-6f)
#define PC1 (-0.99984773f)
#define PC2 ( 0.49737292f)
#define PC3 (-0.31574592f)
#define PC4 ( 0.19035072f)
#define PC5 (-0.08269517f)
#define PC6 ( 0.01741517f)
#define NEG_L2E (-1.4426950408889634f)

__device__ __forceinline__ float lsig(float x) {   // exact-ish, used on tiny arrays only
    return fminf(x, 0.0f) - __logf(1.0f + __expf(-fabsf(x)));
}

// ---- kernel 0: fold projection weights through Wc; bias constants ----
__global__ void prep_kernel(const float* __restrict__ W0, const float* __restrict__ b0,
                            const float* __restrict__ W1, const float* __restrict__ b1,
                            const float* __restrict__ Wc, const float* __restrict__ bc) {
    int i = threadIdx.x;  // 0..255
    float a0 = 0.f, a1 = 0.f;
    #pragma unroll 8
    for (int d = 0; d < 128; d++) {
        a0 += W0[d * IN + i] * Wc[d];
        a1 += W1[d * IN + i] * Wc[128 + d];
    }
    g_v0[i] = a0;
    g_v1[i] = a1;

    int w = i >> 5, l = i & 31;
    if (w == 0) {
        float c = 0.f;
        for (int d = l; d < 128; d += 32) c += b0[d] * Wc[d];
        #pragma unroll
        for (int o = 16; o; o >>= 1) c += __shfl_down_sync(0xffffffffu, c, o);
        if (l == 0) g_consts[0] = c;
    } else if (w == 1) {
        float c = 0.f;
        for (int d = l; d < 128; d += 32) c += b1[d] * Wc[128 + d];
        #pragma unroll
        for (int o = 16; o; o >>= 1) c += __shfl_down_sync(0xffffffffu, c, o);
        if (l == 0) g_consts[1] = c + bc[0];
    }
}

// ---- kernel 1: per-row dot products; one warp per row ----
__global__ void rows_kernel(const float* __restrict__ d0, const float* __restrict__ d1,
                            const float* __restrict__ Wm, const float* __restrict__ bm) {
    int which = blockIdx.y;
    const float* desc = which ? d1 : d0;
    const float* v    = which ? g_v1 : g_v0;
    int warp = threadIdx.x >> 5, lane = threadIdx.x & 31;
    int row = blockIdx.x * 8 + warp;

    const float4* dp = (const float4*)(desc + (size_t)row * IN);
    const float4* vp = (const float4*)v;
    const float4* wp = (const float4*)Wm;

    float as = 0.f, az = 0.f;
    #pragma unroll
    for (int j = 0; j < 2; j++) {
        int k = lane + j * 32;
        float4 dv = dp[k];
        float4 vv = vp[k];
        float4 wv = wp[k];
        as += dv.x * vv.x + dv.y * vv.y + dv.z * vv.z + dv.w * vv.w;
        az += dv.x * wv.x + dv.y * wv.y + dv.z * wv.z + dv.w * wv.w;
    }
    #pragma unroll
    for (int o = 16; o; o >>= 1) {
        as += __shfl_down_sync(0xffffffffu, as, o);
        az += __shfl_down_sync(0xffffffffu, az, o);
    }
    if (lane == 0) {
        float z = az + bm[0];
        if (which == 0) {
            g_s0[row]   = as + g_consts[0];
            g_ls0[row]  = lsig(z);
            g_lsn0[row] = lsig(-z);
        } else {
            g_s1b[row]  = as + g_consts[1];
            g_ls1[row]  = lsig(z);
            g_lsn1[row] = lsig(-z);
        }
    }
}

// packed log-sigmoid pair: out = min(c,0) - log1p(exp(-|c|)) + q   (2 lanes)
__device__ __forceinline__ float2 lsig2(ull c2, ull q2,
                                        ull K1, ull K2, ull K3, ull K4, ull K5, ull K6) {
    float2 c = upk2(c2);
    float ul = ex2_(fabsf(c.x) * NEG_L2E);
    float uh = ex2_(fabsf(c.y) * NEG_L2E);
    ull u2 = pk2(ul, uh);
    ull p  = fma2_(K6, u2, K5);
    p = fma2_(p, u2, K4);
    p = fma2_(p, u2, K3);
    p = fma2_(p, u2, K2);
    p = fma2_(p, u2, K1);
    p = fma2_(p, u2, pk2(PC0, PC0));     // p = -log1p(u)
    ull m2 = pk2(fminf(c.x, 0.f), fminf(c.y, 0.f));
    return upk2(add2_(add2_(m2, p), q2));
}

// ---- kernel 2: fused probs + corres + right edge ----
// probs mapping: thread t -> cols n0+t+j*256 (scalar coalesced STG, stride 2049 rows).
// corres mapping: thread t -> cols n0+4t..4t+3 (STG.128, stride 2048 rows).
__global__ void __launch_bounds__(256) fused_kernel(float* __restrict__ probs,
                                                    float* __restrict__ corres,
                                                    int has_corres) {
    int b  = blockIdx.z;
    int m0 = blockIdx.y * TM;
    int n0 = blockIdx.x * TN;
    int tx = threadIdx.x;

    __shared__ float sh_s0[TM];
    __shared__ float sh_ls0[TM];
    if (tx < TM) {
        int r = b * M + m0 + tx;
        sh_s0[tx]  = g_s0[r];
        sh_ls0[tx] = g_ls0[r];
    }

    float s1v[4], ls1v[4];
    #pragma unroll
    for (int j = 0; j < 4; j++) {
        int n = n0 + tx + j * 256;
        s1v[j]  = g_s1b[b * N + n];
        ls1v[j] = g_ls1[b * N + n];
    }
    ull s1A = pk2(s1v[0], s1v[1]),  s1B = pk2(s1v[2], s1v[3]);
    ull lsA = pk2(ls1v[0], ls1v[1]), lsB = pk2(ls1v[2], ls1v[3]);
    float4 s1c = *(const float4*)(g_s1b + b * N + n0 + 4 * tx);
    __syncthreads();

    const ull K1 = pk2(PC1, PC1), K2 = pk2(PC2, PC2), K3 = pk2(PC3, PC3);
    const ull K4 = pk2(PC4, PC4), K5 = pk2(PC5, PC5), K6 = pk2(PC6, PC6);

    size_t pbase = (size_t)b * (M + 1) * (N + 1);
    float*  prow = probs + pbase + (size_t)m0 * (N + 1) + n0 + tx;
    float4* crow = (float4*)(corres + (size_t)b * M * N + (size_t)m0 * N + n0) + tx;
    const bool wc = (has_corres != 0);

    #pragma unroll 2
    for (int r = 0; r < TM; r++) {
        float s0 = sh_s0[r];
        float l0 = sh_ls0[r];

        if (wc) {
            *crow = make_float4(s0 + s1c.x, s0 + s1c.y, s0 + s1c.z, s0 + s1c.w);
            crow += N / 4;
        }

        ull s0d = pk2(s0, s0);
        ull l0d = pk2(l0, l0);
        float2 ra = lsig2(add2_(s0d, s1A), add2_(l0d, lsA), K1, K2, K3, K4, K5, K6);
        float2 rb = lsig2(add2_(s0d, s1B), add2_(l0d, lsB), K1, K2, K3, K4, K5, K6);
        prow[0]   = ra.x;
        prow[256] = ra.y;
        prow[512] = rb.x;
        prow[768] = rb.y;
        prow += (N + 1);
    }

    // fused right-edge column: probs[b, m0..m0+TM-1, N] = logsig(-z0)
    if (blockIdx.x == (N / TN - 1) && tx < TM) {
        probs[pbase + (size_t)(m0 + tx) * (N + 1) + N] = g_lsn0[b * M + m0 + tx];
    }
}

// ---- kernel 3: bottom row of probs (coalesced) ----
__global__ void bottom_kernel(float* __restrict__ probs) {
    int idx = blockIdx.x * blockDim.x + threadIdx.x;  // over B*(N+1)
    if (idx >= B * (N + 1)) return;
    int b = idx / (N + 1), n = idx % (N + 1);
    size_t pbase = (size_t)b * (M + 1) * (N + 1) + (size_t)M * (N + 1);
    probs[pbase + n] = (n < N) ? g_lsn1[b * N + n] : 0.0f;
}

extern "C" void kernel_launch(void* const* d_in, const int* in_sizes, int n_in,
                              void* d_out, int out_size) {
    const float* desc0 = (const float*)d_in[0];
    const float* desc1 = (const float*)d_in[1];
    const float* W0    = (const float*)d_in[2];
    const float* b0    = (const float*)d_in[3];
    const float* W1    = (const float*)d_in[4];
    const float* b1    = (const float*)d_in[5];
    const float* Wm    = (const float*)d_in[6];
    const float* bm    = (const float*)d_in[7];
    const float* Wc    = (const float*)d_in[8];
    const float* bc    = (const float*)d_in[9];

    float* out = (float*)d_out;
    long long probs_elems  = (long long)B * (M + 1) * (N + 1);
    long long corres_elems = (long long)B * M * N;
    int has_corres = ((long long)out_size >= probs_elems + corres_elems) ? 1 : 0;
    float* probs  = out;
    float* corres = out + probs_elems;

    prep_kernel<<<1, 256>>>(W0, b0, W1, b1, Wc, bc);
    rows_kernel<<<dim3(B * M / 8, 2), 256>>>(desc0, desc1, Wm, bm);
    fused_kernel<<<dim3(N / TN, M / TM, B), 256>>>(probs, corres, has_corres);
    bottom_kernel<<<(B * (N + 1) + 255) / 256, 256>>>(probs);
}

// round 5
// speedup vs baseline: 1.2292x; 1.2030x over previous
#include <cuda_runtime.h>

#define B 8
#define M 2048
#define N 2048
#define IN 256
#define TM 8
#define TN 1024

// ---- scratch (allocation-free: __device__ globals) ----
__device__ float g_v0[IN];
__device__ float g_v1[IN];
__device__ float g_consts[2];
__device__ float g_s0[B * M];       // s0 + const0
__device__ float g_ls0[B * M];      // logsig(z0)
__device__ float g_lsn0[B * M];     // logsig(-z0)
__device__ float g_s1b[B * N];      // s1 + const1 (bc folded)
__device__ float g_ls1[B * N];      // logsig(z1)
__device__ float g_lsn1[B * N];     // logsig(-z1)

// Negated coefficients of deg-6 poly for ln(1+u), u in [0,1]
// (shifted-Chebyshev expansion; abs err < ~5e-6).
#define PC0 (-1.79e-6f)
#define PC1 (-0.99984773f)
#define PC2 ( 0.49737292f)
#define PC3 (-0.31574592f)
#define PC4 ( 0.19035072f)
#define PC5 (-0.08269517f)
#define PC6 ( 0.01741517f)
#define NEG_L2E (-1.4426950408889634f)

__device__ __forceinline__ float ex2_(float x) {
    float r; asm("ex2.approx.f32 %0, %1;" : "=f"(r) : "f"(x)); return r;
}

__device__ __forceinline__ float lsig(float x) {   // reference-accurate, tiny arrays only
    return fminf(x, 0.0f) - __logf(1.0f + __expf(-fabsf(x)));
}

// fast scalar log-sigmoid + q:  min(c,0) - log1p(exp(-|c|)) + q
__device__ __forceinline__ float lsig_fast(float c, float q) {
    float u = ex2_(fabsf(c) * NEG_L2E);          // exp(-|c|), 1 MUFU
    float p = fmaf(PC6, u, PC5);
    p = fmaf(p, u, PC4);
    p = fmaf(p, u, PC3);
    p = fmaf(p, u, PC2);
    p = fmaf(p, u, PC1);
    p = fmaf(p, u, PC0);                         // p = -log1p(u)
    return fminf(c, 0.0f) + p + q;
}

// ---- kernel 0: fold projection weights through Wc; bias constants ----
__global__ void prep_kernel(const float* __restrict__ W0, const float* __restrict__ b0,
                            const float* __restrict__ W1, const float* __restrict__ b1,
                            const float* __restrict__ Wc, const float* __restrict__ bc) {
    int i = threadIdx.x;  // 0..255
    float a0 = 0.f, a1 = 0.f;
    #pragma unroll 8
    for (int d = 0; d < 128; d++) {
        a0 += W0[d * IN + i] * Wc[d];
        a1 += W1[d * IN + i] * Wc[128 + d];
    }
    g_v0[i] = a0;
    g_v1[i] = a1;

    int w = i >> 5, l = i & 31;
    if (w == 0) {
        float c = 0.f;
        for (int d = l; d < 128; d += 32) c += b0[d] * Wc[d];
        #pragma unroll
        for (int o = 16; o; o >>= 1) c += __shfl_down_sync(0xffffffffu, c, o);
        if (l == 0) g_consts[0] = c;
    } else if (w == 1) {
        float c = 0.f;
        for (int d = l; d < 128; d += 32) c += b1[d] * Wc[128 + d];
        #pragma unroll
        for (int o = 16; o; o >>= 1) c += __shfl_down_sync(0xffffffffu, c, o);
        if (l == 0) g_consts[1] = c + bc[0];
    }
}

// ---- kernel 1: per-row dot products; one warp per row ----
__global__ void rows_kernel(const float* __restrict__ d0, const float* __restrict__ d1,
                            const float* __restrict__ Wm, const float* __restrict__ bm) {
    int which = blockIdx.y;
    const float* desc = which ? d1 : d0;
    const float* v    = which ? g_v1 : g_v0;
    int warp = threadIdx.x >> 5, lane = threadIdx.x & 31;
    int row = blockIdx.x * 8 + warp;

    const float4* dp = (const float4*)(desc + (size_t)row * IN);
    const float4* vp = (const float4*)v;
    const float4* wp = (const float4*)Wm;

    float as = 0.f, az = 0.f;
    #pragma unroll
    for (int j = 0; j < 2; j++) {
        int k = lane + j * 32;
        float4 dv = dp[k];
        float4 vv = vp[k];
        float4 wv = wp[k];
        as += dv.x * vv.x + dv.y * vv.y + dv.z * vv.z + dv.w * vv.w;
        az += dv.x * wv.x + dv.y * wv.y + dv.z * wv.z + dv.w * wv.w;
    }
    #pragma unroll
    for (int o = 16; o; o >>= 1) {
        as += __shfl_down_sync(0xffffffffu, as, o);
        az += __shfl_down_sync(0xffffffffu, az, o);
    }
    if (lane == 0) {
        float z = az + bm[0];
        if (which == 0) {
            g_s0[row]   = as + g_consts[0];
            g_ls0[row]  = lsig(z);
            g_lsn0[row] = lsig(-z);
        } else {
            g_s1b[row]  = as + g_consts[1];
            g_ls1[row]  = lsig(z);
            g_lsn1[row] = lsig(-z);
        }
    }
}

// ---- kernel 2: fused probs + corres + right edge + bottom row ----
// probs mapping: thread t -> cols n0+t+j*256 (coalesced scalar STG; row stride 2049).
// corres mapping: thread t -> cols n0+4t..4t+3 (STG.128; row stride 2048).
__global__ void __launch_bounds__(256) fused_kernel(float* __restrict__ probs,
                                                    float* __restrict__ corres,
                                                    int has_corres) {
    int b  = blockIdx.z;
    int m0 = blockIdx.y * TM;
    int n0 = blockIdx.x * TN;
    int tx = threadIdx.x;

    __shared__ float sh_s0[TM];
    __shared__ float sh_ls0[TM];
    if (tx < TM) {
        int r = b * M + m0 + tx;
        sh_s0[tx]  = g_s0[r];
        sh_ls0[tx] = g_ls0[r];
    }

    float s1v[4], ls1v[4];
    #pragma unroll
    for (int j = 0; j < 4; j++) {
        int n = n0 + tx + j * 256;
        s1v[j]  = g_s1b[b * N + n];
        ls1v[j] = g_ls1[b * N + n];
    }
    float4 s1c = *(const float4*)(g_s1b + b * N + n0 + 4 * tx);
    __syncthreads();

    size_t pbase = (size_t)b * (M + 1) * (N + 1);
    float*  prow = probs + pbase + (size_t)m0 * (N + 1) + n0 + tx;
    float4* crow = (float4*)(corres + (size_t)b * M * N + (size_t)m0 * N + n0) + tx;
    const bool wc = (has_corres != 0);

    #pragma unroll
    for (int r = 0; r < TM; r++) {
        float s0 = sh_s0[r];
        float l0 = sh_ls0[r];

        if (wc) {
            *crow = make_float4(s0 + s1c.x, s0 + s1c.y, s0 + s1c.z, s0 + s1c.w);
            crow += N / 4;
        }

        prow[0]   = lsig_fast(s0 + s1v[0], l0 + ls1v[0]);
        prow[256] = lsig_fast(s0 + s1v[1], l0 + ls1v[1]);
        prow[512] = lsig_fast(s0 + s1v[2], l0 + ls1v[2]);
        prow[768] = lsig_fast(s0 + s1v[3], l0 + ls1v[3]);
        prow += (N + 1);
    }

    // fused right-edge column: probs[b, m0..m0+TM-1, N] = logsig(-z0)
    if (blockIdx.x == (N / TN - 1) && tx < TM) {
        probs[pbase + (size_t)(m0 + tx) * (N + 1) + N] = g_lsn0[b * M + m0 + tx];
    }

    // fused bottom row (+ corner): blocks in the last row stripe write row M
    if (blockIdx.y == (M / TM - 1)) {
        float* brow = probs + pbase + (size_t)M * (N + 1);
        #pragma unroll
        for (int j = 0; j < 4; j++) {
            int n = n0 + tx + j * 256;
            brow[n] = g_lsn1[b * N + n];
        }
        if (blockIdx.x == (N / TN - 1) && tx == 0) brow[N] = 0.0f;
    }
}

extern "C" void kernel_launch(void* const* d_in, const int* in_sizes, int n_in,
                              void* d_out, int out_size) {
    const float* desc0 = (const float*)d_in[0];
    const float* desc1 = (const float*)d_in[1];
    const float* W0    = (const float*)d_in[2];
    const float* b0    = (const float*)d_in[3];
    const float* W1    = (const float*)d_in[4];
    const float* b1    = (const float*)d_in[5];
    const float* Wm    = (const float*)d_in[6];
    const float* bm    = (const float*)d_in[7];
    const float* Wc    = (const float*)d_in[8];
    const float* bc    = (const float*)d_in[9];

    float* out = (float*)d_out;
    long long probs_elems  = (long long)B * (M + 1) * (N + 1);
    long long corres_elems = (long long)B * M * N;
    int has_corres = ((long long)out_size >= probs_elems + corres_elems) ? 1 : 0;
    float* probs  = out;
    float* corres = out + probs_elems;

    prep_kernel<<<1, 256>>>(W0, b0, W1, b1, Wc, bc);
    rows_kernel<<<dim3(B * M / 8, 2), 256>>>(desc0, desc1, Wm, bm);
    fused_kernel<<<dim3(N / TN, M / TM, B), 256>>>(probs, corres, has_corres);
}

// round 7
// speedup vs baseline: 1.5166x; 1.2339x over previous
#include <cuda_runtime.h>

#define B 8
#define M 2048
#define N 2048
#define IN 256
#define TM 8
#define TN 1024
#define NCHUNK 8
#define DCHUNK 16   // 128 / NCHUNK

// ---- scratch (allocation-free: __device__ globals) ----
__device__ float g_vp[2][NCHUNK][IN];   // partial folds of W^T @ Wc half
__device__ float g_consts[2];
__device__ float g_s0[B * M];       // s0 + const0
__device__ float g_ls0[B * M];      // logsig(z0)
__device__ float g_lsn0[B * M];     // logsig(-z0)
__device__ float g_s1b[B * N];      // s1 + const1 (bc folded)
__device__ float g_ls1[B * N];      // logsig(z1)
__device__ float g_lsn1[B * N];     // logsig(-z1)

// Negated coefficients of deg-6 poly for ln(1+u), u in [0,1]
#define PC0 (-1.79e-6f)
#define PC1 (-0.99984773f)
#define PC2 ( 0.49737292f)
#define PC3 (-0.31574592f)
#define PC4 ( 0.19035072f)
#define PC5 (-0.08269517f)
#define PC6 ( 0.01741517f)
#define NEG_L2E (-1.4426950408889634f)

__device__ __forceinline__ float ex2_(float x) {
    float r; asm("ex2.approx.f32 %0, %1;" : "=f"(r) : "f"(x)); return r;
}

__device__ __forceinline__ float lsig(float x) {   // reference-accurate, tiny arrays only
    return fminf(x, 0.0f) - __logf(1.0f + __expf(-fabsf(x)));
}

// fast scalar log-sigmoid + q:  min(c,0) - log1p(exp(-|c|)) + q
__device__ __forceinline__ float lsig_fast(float c, float q) {
    float u = ex2_(fabsf(c) * NEG_L2E);          // exp(-|c|), 1 MUFU
    float p = fmaf(PC6, u, PC5);
    p = fmaf(p, u, PC4);
    p = fmaf(p, u, PC3);
    p = fmaf(p, u, PC2);
    p = fmaf(p, u, PC1);
    p = fmaf(p, u, PC0);                         // p = -log1p(u)
    return fminf(c, 0.0f) + p + q;
}

// ---- kernel 0: partial fold of projection weights through Wc ----
// grid (NCHUNK, 2): block (c, which) folds d = c*DCHUNK .. +DCHUNK-1.
// Loads fully coalesced (256 threads sweep one 1KB W row per d).
__global__ void prep_kernel(const float* __restrict__ W0, const float* __restrict__ b0,
                            const float* __restrict__ W1, const float* __restrict__ b1,
                            const float* __restrict__ Wc, const float* __restrict__ bc) {
    int i = threadIdx.x;             // 0..255 (output column)
    int chunk = blockIdx.x;
    int which = blockIdx.y;
    const float* W  = which ? W1 : W0;
    const float* wc = Wc + which * 128;

    float a = 0.f;
    int d0 = chunk * DCHUNK;
    #pragma unroll
    for (int dd = 0; dd < DCHUNK; dd++) {
        int d = d0 + dd;
        a += W[d * IN + i] * wc[d];
    }
    g_vp[which][chunk][i] = a;

    // chunk-0 blocks also compute the bias constants (one warp each)
    if (chunk == 0 && i < 32) {
        const float* bias = which ? b1 : b0;
        float c = 0.f;
        #pragma unroll
        for (int d = i; d < 128; d += 32) c += bias[d] * wc[d];
        #pragma unroll
        for (int o = 16; o; o >>= 1) c += __shfl_down_sync(0xffffffffu, c, o);
        if (i == 0) g_consts[which] = which ? (c + bc[0]) : c;
    }
}

// ---- kernel 1: per-row dot products; one warp per row ----
__global__ void rows_kernel(const float* __restrict__ d0, const float* __restrict__ d1,
                            const float* __restrict__ Wm, const float* __restrict__ bm) {
    int which = blockIdx.y;
    const float* desc = which ? d1 : d0;
    int warp = threadIdx.x >> 5, lane = threadIdx.x & 31;
    int row = blockIdx.x * 8 + warp;

    // reduce the NCHUNK partial folds into smem v[256]
    __shared__ float sh_v[IN];
    {
        float a = 0.f;
        #pragma unroll
        for (int c = 0; c < NCHUNK; c++) a += g_vp[which][c][threadIdx.x];
        sh_v[threadIdx.x] = a;
    }
    __syncthreads();

    const float4* dp = (const float4*)(desc + (size_t)row * IN);
    const float4* vp = (const float4*)sh_v;
    const float4* wp = (const float4*)Wm;

    float as = 0.f, az = 0.f;
    #pragma unroll
    for (int j = 0; j < 2; j++) {
        int k = lane + j * 32;
        float4 dv = dp[k];
        float4 vv = vp[k];
        float4 wv = wp[k];
        as += dv.x * vv.x + dv.y * vv.y + dv.z * vv.z + dv.w * vv.w;
        az += dv.x * wv.x + dv.y * wv.y + dv.z * wv.z + dv.w * wv.w;
    }
    #pragma unroll
    for (int o = 16; o; o >>= 1) {
        as += __shfl_down_sync(0xffffffffu, as, o);
        az += __shfl_down_sync(0xffffffffu, az, o);
    }
    if (lane == 0) {
        float z = az + bm[0];
        if (which == 0) {
            g_s0[row]   = as + g_consts[0];
            g_ls0[row]  = lsig(z);
            g_lsn0[row] = lsig(-z);
        } else {
            g_s1b[row]  = as + g_consts[1];
            g_ls1[row]  = lsig(z);
            g_lsn1[row] = lsig(-z);
        }
    }
}

// ---- kernel 2: fused probs + corres + right edge + bottom row ----
// probs mapping: thread t -> cols n0+t+j*256 (coalesced scalar STG; row stride 2049).
// corres mapping: thread t -> cols n0+4t..4t+3 (STG.128; row stride 2048).
__global__ void __launch_bounds__(256) fused_kernel(float* __restrict__ probs,
                                                    float* __restrict__ corres,
                                                    int has_corres) {
    int b  = blockIdx.z;
    int m0 = blockIdx.y * TM;
    int n0 = blockIdx.x * TN;
    int tx = threadIdx.x;

    __shared__ float sh_s0[TM];
    __shared__ float sh_ls0[TM];
    if (tx < TM) {
        int r = b * M + m0 + tx;
        sh_s0[tx]  = g_s0[r];
        sh_ls0[tx] = g_ls0[r];
    }

    float s1v[4], ls1v[4];
    #pragma unroll
    for (int j = 0; j < 4; j++) {
        int n = n0 + tx + j * 256;
        s1v[j]  = g_s1b[b * N + n];
        ls1v[j] = g_ls1[b * N + n];
    }
    float4 s1c = *(const float4*)(g_s1b + b * N + n0 + 4 * tx);
    __syncthreads();

    size_t pbase = (size_t)b * (M + 1) * (N + 1);
    float*  prow = probs + pbase + (size_t)m0 * (N + 1) + n0 + tx;
    float4* crow = (float4*)(corres + (size_t)b * M * N + (size_t)m0 * N + n0) + tx;
    const bool wc = (has_corres != 0);

    #pragma unroll
    for (int r = 0; r < TM; r++) {
        float s0 = sh_s0[r];
        float l0 = sh_ls0[r];

        if (wc) {
            *crow = make_float4(s0 + s1c.x, s0 + s1c.y, s0 + s1c.z, s0 + s1c.w);
            crow += N / 4;
        }

        prow[0]   = lsig_fast(s0 + s1v[0], l0 + ls1v[0]);
        prow[256] = lsig_fast(s0 + s1v[1], l0 + ls1v[1]);
        prow[512] = lsig_fast(s0 + s1v[2], l0 + ls1v[2]);
        prow[768] = lsig_fast(s0 + s1v[3], l0 + ls1v[3]);
        prow += (N + 1);
    }

    // fused right-edge column: probs[b, m0..m0+TM-1, N] = logsig(-z0)
    if (blockIdx.x == (N / TN - 1) && tx < TM) {
        probs[pbase + (size_t)(m0 + tx) * (N + 1) + N] = g_lsn0[b * M + m0 + tx];
    }

    // fused bottom row (+ corner): blocks in the last row stripe write row M
    if (blockIdx.y == (M / TM - 1)) {
        float* brow = probs + pbase + (size_t)M * (N + 1);
        #pragma unroll
        for (int j = 0; j < 4; j++) {
            int n = n0 + tx + j * 256;
            brow[n] = g_lsn1[b * N + n];
        }
        if (blockIdx.x == (N / TN - 1) && tx == 0) brow[N] = 0.0f;
    }
}

extern "C" void kernel_launch(void* const* d_in, const int* in_sizes, int n_in,
                              void* d_out, int out_size) {
    const float* desc0 = (const float*)d_in[0];
    const float* desc1 = (const float*)d_in[1];
    const float* W0    = (const float*)d_in[2];
    const float* b0    = (const float*)d_in[3];
    const float* W1    = (const float*)d_in[4];
    const float* b1    = (const float*)d_in[5];
    const float* Wm    = (const float*)d_in[6];
    const float* bm    = (const float*)d_in[7];
    const float* Wc    = (const float*)d_in[8];
    const float* bc    = (const float*)d_in[9];

    float* out = (float*)d_out;
    long long probs_elems  = (long long)B * (M + 1) * (N + 1);
    long long corres_elems = (long long)B * M * N;
    int has_corres = ((long long)out_size >= probs_elems + corres_elems) ? 1 : 0;
    float* probs  = out;
    float* corres = out + probs_elems;

    prep_kernel<<<dim3(NCHUNK, 2), 256>>>(W0, b0, W1, b1, Wc, bc);
    rows_kernel<<<dim3(B * M / 8, 2), 256>>>(desc0, desc1, Wm, bm);
    fused_kernel<<<dim3(N / TN, M / TM, B), 256>>>(probs, corres, has_corres);
}